// round 4
// baseline (speedup 1.0000x reference)
#include <cuda_runtime.h>

#define NN 20000

// ---------------- device scratch ----------------
__device__ float g_z1 [NN * 64];
__device__ float g_hd1[NN * 64];
__device__ float g_zc [NN * 64];
__device__ float g_u  [NN * 64];

// ---------------- helpers ----------------
__device__ __forceinline__ float warpSumAll(float v) {
#pragma unroll
    for (int o = 16; o > 0; o >>= 1) v += __shfl_xor_sync(0xffffffffu, v, o);
    return v;
}
__device__ __forceinline__ float warpMaxAll(float v) {
#pragma unroll
    for (int o = 16; o > 0; o >>= 1) v = fmaxf(v, __shfl_xor_sync(0xffffffffu, v, o));
    return v;
}
__device__ __forceinline__ float lrelu(float x) { return x > 0.f ? x : 0.01f * x; }

__device__ __forceinline__ float eluf(float x) {
    if (x > 0.f) return x;
    if (x > -0.25f)
        return x * (1.f + x * (0.5f + x * (0.16666667f + x * 0.041666667f)));
    return __expf(x) - 1.f;
}

union F2U { float2 f; unsigned long long u; };
// c += a * b elementwise (packed dual-fp32 FMA); a comes pre-duplicated from smem
__device__ __forceinline__ void fma2(float2& c, float2 a, float2 b) {
    F2U A, B, C; A.f = a; B.f = b; C.f = c;
    asm("fma.rn.f32x2 %0, %1, %2, %0;" : "+l"(C.u) : "l"(A.u), "l"(B.u));
    c = C.f;
}

// =====================================================================
// GEMM design: block=256 (8 warps), 32 nodes/block (grid=625), warp -> 4 nodes.
// Lane l owns output dims {2l, 2l+1} (pair0) and {2l+64, 2l+65} (pair1).
// A staged DUPLICATED in smem: As2[row][k] = (a,a)  -> LDS.64 broadcast is an
// FFMA2-ready operand, zero splat MOVs. W staged k-major lane-interleaved:
// Ws[k][4l..4l+3] -> one LDS.128 per k per lane.
// =====================================================================

// ---------------- encoder GEMM: Z = h@fcE^T, HD = h@dfE^T ----------------
__global__ __launch_bounds__(256, 4) void gemm_enc(const float* __restrict__ A,
                                                   const float* __restrict__ fcE,
                                                   const float* __restrict__ dfE,
                                                   float* __restrict__ Z,
                                                   float* __restrict__ HD) {
    __shared__ __align__(16) float2 As2[32][32];
    __shared__ __align__(16) float  Ws[32][132];

    const int t = threadIdx.x, lane = t & 31, w = t >> 5;
    const int node0 = blockIdx.x * 32;

    float2 acc[4][2];
#pragma unroll
    for (int i = 0; i < 4; i++) { acc[i][0] = make_float2(0.f, 0.f); acc[i][1] = make_float2(0.f, 0.f); }

    for (int ch = 0; ch < 4; ch++) {
        const int kk = ch * 32;
#pragma unroll
        for (int idx = t; idx < 32 * 32; idx += 256) {
            int row = idx >> 5, k = idx & 31;
            float v = A[(node0 + row) * 128 + kk + k];
            As2[row][k] = make_float2(v, v);
        }
#pragma unroll
        for (int idx = t; idx < 128 * 32; idx += 256) {
            int od = idx >> 5, k = idx & 31;
            float v = (od < 64) ? fcE[od * 128 + kk + k] : dfE[(od - 64) * 128 + kk + k];
            int l2  = (od & 63) >> 1;
            int sub = ((od >> 6) << 1) | (od & 1);
            Ws[k][4 * l2 + sub] = v;
        }
        __syncthreads();

#pragma unroll
        for (int k = 0; k < 32; k += 2) {
            const float4 wv0 = *(const float4*)&Ws[k][4 * lane];
            const float4 wv1 = *(const float4*)&Ws[k + 1][4 * lane];
            const float2 p00 = make_float2(wv0.x, wv0.y), p01 = make_float2(wv0.z, wv0.w);
            const float2 p10 = make_float2(wv1.x, wv1.y), p11 = make_float2(wv1.z, wv1.w);
#pragma unroll
            for (int i = 0; i < 4; i++) {
                const float2 a0 = As2[w * 4 + i][k];
                const float2 a1 = As2[w * 4 + i][k + 1];
                fma2(acc[i][0], a0, p00);
                fma2(acc[i][1], a0, p01);
                fma2(acc[i][0], a1, p10);
                fma2(acc[i][1], a1, p11);
            }
        }
        __syncthreads();
    }

#pragma unroll
    for (int i = 0; i < 4; i++) {
        int node = node0 + w * 4 + i;
        ((float2*)(Z  + node * 64))[lane] = acc[i][0];
        ((float2*)(HD + node * 64))[lane] = acc[i][1];
    }
}

// ---------------- decoder GEMM: out = zc@fcD^T + u@diffD^T ----------------
__global__ __launch_bounds__(256, 4) void gemm_dec(const float* __restrict__ fcD,
                                                   const float* __restrict__ diffD,
                                                   float* __restrict__ out) {
    __shared__ __align__(16) float2 As2[32][32];
    __shared__ __align__(16) float  Ws[32][132];

    const int t = threadIdx.x, lane = t & 31, w = t >> 5;
    const int node0 = blockIdx.x * 32;

    float2 acc[4][2];
#pragma unroll
    for (int i = 0; i < 4; i++) { acc[i][0] = make_float2(0.f, 0.f); acc[i][1] = make_float2(0.f, 0.f); }

    for (int ch = 0; ch < 4; ch++) {
        const float* Asrc = (ch < 2) ? g_zc : g_u;
        const float* Wsrc = (ch < 2) ? fcD : diffD;
        const int kk = (ch & 1) * 32;
#pragma unroll
        for (int idx = t; idx < 32 * 32; idx += 256) {
            int row = idx >> 5, k = idx & 31;
            float v = Asrc[(node0 + row) * 64 + kk + k];
            As2[row][k] = make_float2(v, v);
        }
#pragma unroll
        for (int idx = t; idx < 128 * 32; idx += 256) {
            int od = idx >> 5, k = idx & 31;
            float v = Wsrc[od * 64 + kk + k];
            int l2  = (od & 63) >> 1;
            int sub = ((od >> 6) << 1) | (od & 1);
            Ws[k][4 * l2 + sub] = v;
        }
        __syncthreads();

#pragma unroll
        for (int k = 0; k < 32; k += 2) {
            const float4 wv0 = *(const float4*)&Ws[k][4 * lane];
            const float4 wv1 = *(const float4*)&Ws[k + 1][4 * lane];
            const float2 p00 = make_float2(wv0.x, wv0.y), p01 = make_float2(wv0.z, wv0.w);
            const float2 p10 = make_float2(wv1.x, wv1.y), p11 = make_float2(wv1.z, wv1.w);
#pragma unroll
            for (int i = 0; i < 4; i++) {
                const float2 a0 = As2[w * 4 + i][k];
                const float2 a1 = As2[w * 4 + i][k + 1];
                fma2(acc[i][0], a0, p00);
                fma2(acc[i][1], a0, p01);
                fma2(acc[i][0], a1, p10);
                fma2(acc[i][1], a1, p11);
            }
        }
        __syncthreads();
    }

#pragma unroll
    for (int i = 0; i < 4; i++) {
        int node = node0 + w * 4 + i;
        ((float2*)(out + node * 128))[lane]      = acc[i][0];
        ((float2*)(out + node * 128 + 64))[lane] = acc[i][1];
    }
}

// ---------------- encoder aggregation: 3 hops + hop-attention combine ----------------
__global__ __launch_bounds__(256) void enc_agg(const float* __restrict__ attE,
                                               const float* __restrict__ attC) {
    __shared__ __align__(16) float hdT[56][66];
    __shared__ float sT[56];
    __shared__ __align__(16) float wS[3][25][36];
    __shared__ float sAe[64], sAc[64];

    const int t = threadIdx.x, w = t >> 5, lane = t & 31;
    const int nodeBase = blockIdx.x * 32;
    const int nl0 = w * 4;

    if (t < 64) { sAe[t] = attE[t]; sAc[t] = attC[t]; }

    for (int r = w; r < 56; r += 8) {
        int g = nodeBase - 24 + r;
        if (g < 0) g += NN;
        ((float2*)hdT[r])[lane] = ((const float2*)(g_hd1 + g * 64))[lane];
    }
    __syncthreads();

    for (int r = w; r < 56; r += 8) {
        float2 hv = ((float2*)hdT[r])[lane];
        float p = warpSumAll(hv.x * sAe[2 * lane] + hv.y * sAe[2 * lane + 1]);
        if (lane == 0) sT[r] = p;
    }
    __syncthreads();

#pragma unroll
    for (int j = 0; j < 4; j++) {
        const int li = 24 + nl0 + j;
        const float s_i = sT[li];
        float el = (lane < 25) ? lrelu(sT[li - lane] - s_i) : -1e30f;
        const float m1 = warpMaxAll(lane < 9  ? el : -1e30f);
        const float m2 = warpMaxAll(lane < 17 ? el : -1e30f);
        const float m3 = warpMaxAll(el);
        const float ex1 = (lane < 9)  ? __expf(el - m1) : 0.f;
        const float ex2 = (lane < 17) ? __expf(el - m2) : 0.f;
        const float ex3 = (lane < 25) ? __expf(el - m3) : 0.f;
        const float r1 = 1.f / warpSumAll(ex1);
        const float r2 = 1.f / warpSumAll(ex2);
        const float r3 = 1.f / warpSumAll(ex3);
        if (lane < 25) {
            wS[0][lane][nl0 + j] = ex1 * r1;
            wS[1][lane][nl0 + j] = ex2 * r2;
            wS[2][lane][nl0 + j] = ex3 * r3;
        }
    }
    __syncwarp();

    float2 A[4][3];
#pragma unroll
    for (int j = 0; j < 4; j++)
#pragma unroll
        for (int hh = 0; hh < 3; hh++) A[j][hh] = make_float2(0.f, 0.f);

#pragma unroll
    for (int tt = 0; tt < 25; tt++) {
        const float4 w3 = *(const float4*)&wS[2][tt][nl0];
        float4 w2, w1;
        if (tt < 17) w2 = *(const float4*)&wS[1][tt][nl0];
        if (tt < 9)  w1 = *(const float4*)&wS[0][tt][nl0];
#pragma unroll
        for (int j = 0; j < 4; j++) {
            const float2 hv = ((float2*)hdT[24 + nl0 + j - tt])[lane];
            const float g3 = ((const float*)&w3)[j];
            A[j][2].x = fmaf(g3, hv.x, A[j][2].x);
            A[j][2].y = fmaf(g3, hv.y, A[j][2].y);
            if (tt < 17) {
                const float g2 = ((const float*)&w2)[j];
                A[j][1].x = fmaf(g2, hv.x, A[j][1].x);
                A[j][1].y = fmaf(g2, hv.y, A[j][1].y);
            }
            if (tt < 9) {
                const float g1 = ((const float*)&w1)[j];
                A[j][0].x = fmaf(g1, hv.x, A[j][0].x);
                A[j][0].y = fmaf(g1, hv.y, A[j][0].y);
            }
        }
    }

    const float ac0 = sAc[2 * lane], ac1 = sAc[2 * lane + 1];
#pragma unroll
    for (int j = 0; j < 4; j++) {
        const int li = 24 + nl0 + j;
        const int node = nodeBase + nl0 + j;
        const float2 hvi = ((float2*)hdT[li])[lane];
        const float2 zv  = ((const float2*)(g_z1 + node * 64))[lane];
        float2 Z1, Z2, Z3;
        Z1.x = eluf(zv.x + A[j][0].x - hvi.x); Z1.y = eluf(zv.y + A[j][0].y - hvi.y);
        Z2.x = eluf(zv.x + A[j][1].x - hvi.x); Z2.y = eluf(zv.y + A[j][1].y - hvi.y);
        Z3.x = eluf(zv.x + A[j][2].x - hvi.x); Z3.y = eluf(zv.y + A[j][2].y - hvi.y);

        const float c1 = warpSumAll(Z1.x * ac0 + Z1.y * ac1);
        const float c2 = warpSumAll(Z2.x * ac0 + Z2.y * ac1);
        const float c3 = warpSumAll(Z3.x * ac0 + Z3.y * ac1);
        const float l1 = lrelu(c1), l2 = lrelu(c2), l3 = lrelu(c3);
        const float mx = fmaxf(l1, fmaxf(l2, l3));
        const float e1 = __expf(l1 - mx), e2 = __expf(l2 - mx), e3 = __expf(l3 - mx);
        const float rd = 1.f / (e1 + e2 + e3);

        float2 o;
        o.x = (e1 * Z1.x + e2 * Z2.x + e3 * Z3.x) * rd;
        o.y = (e1 * Z1.y + e2 * Z2.y + e3 * Z3.y) * rd;
        ((float2*)(g_zc + node * 64))[lane] = o;
    }
}

// ---------------- decoder aggregation in 64-dim latent ----------------
__global__ __launch_bounds__(256) void dec_agg(const float* __restrict__ diffD,
                                               const float* __restrict__ attD) {
    __shared__ __align__(16) float zT[56][66];
    __shared__ float sT[56];
    __shared__ __align__(16) float wS[25][36];
    __shared__ float sv[64];

    const int t = threadIdx.x, w = t >> 5, lane = t & 31;
    const int nodeBase = blockIdx.x * 32;
    const int nl0 = w * 4;

    if (t < 64) {
        float a = 0.f;
#pragma unroll 4
        for (int od = 0; od < 128; od++) a = fmaf(diffD[od * 64 + t], attD[od], a);
        sv[t] = a;
    }

    for (int r = w; r < 56; r += 8) {
        int g = nodeBase - 24 + r;
        if (g < 0) g += NN;
        ((float2*)zT[r])[lane] = ((const float2*)(g_zc + g * 64))[lane];
    }
    __syncthreads();

    for (int r = w; r < 56; r += 8) {
        float2 zv = ((float2*)zT[r])[lane];
        float p = warpSumAll(zv.x * sv[2 * lane] + zv.y * sv[2 * lane + 1]);
        if (lane == 0) sT[r] = p;
    }
    __syncthreads();

#pragma unroll
    for (int j = 0; j < 4; j++) {
        const int li = 24 + nl0 + j;
        const float s_i = sT[li];
        float el = (lane < 25) ? lrelu(sT[li - lane] - s_i) : -1e30f;
        const float m = warpMaxAll(el);
        const float ex = (lane < 25) ? __expf(el - m) : 0.f;
        const float rd = 1.f / warpSumAll(ex);
        if (lane < 25) wS[lane][nl0 + j] = ex * rd;
    }
    __syncwarp();

    float2 A[4];
#pragma unroll
    for (int j = 0; j < 4; j++) A[j] = make_float2(0.f, 0.f);

#pragma unroll
    for (int tt = 0; tt < 25; tt++) {
        const float4 wv = *(const float4*)&wS[tt][nl0];
#pragma unroll
        for (int j = 0; j < 4; j++) {
            const float2 zv = ((float2*)zT[24 + nl0 + j - tt])[lane];
            const float g = ((const float*)&wv)[j];
            A[j].x = fmaf(g, zv.x, A[j].x);
            A[j].y = fmaf(g, zv.y, A[j].y);
        }
    }

#pragma unroll
    for (int j = 0; j < 4; j++) {
        const int node = nodeBase + nl0 + j;
        const float2 zvi = ((float2*)zT[24 + nl0 + j])[lane];
        float2 o;
        o.x = A[j].x - zvi.x;
        o.y = A[j].y - zvi.y;
        ((float2*)(g_u + node * 64))[lane] = o;
    }
}

// ---------------- launch ----------------
extern "C" void kernel_launch(void* const* d_in, const int* in_sizes, int n_in,
                              void* d_out, int out_size) {
    const float* h        = (const float*)d_in[0];
    const float* fc_enc   = (const float*)d_in[1];
    const float* diff_enc = (const float*)d_in[2];
    const float* att_enc  = (const float*)d_in[3];
    const float* fc_dec   = (const float*)d_in[4];
    const float* diff_dec = (const float*)d_in[5];
    const float* att_dec  = (const float*)d_in[6];
    const float* att_comb = (const float*)d_in[7];
    float* out = (float*)d_out;

    void *p;
    cudaGetSymbolAddress(&p, g_z1);  float* z1  = (float*)p;
    cudaGetSymbolAddress(&p, g_hd1); float* hd1 = (float*)p;

    gemm_enc<<<NN / 32, 256>>>(h, fc_enc, diff_enc, z1, hd1);
    enc_agg<<<NN / 32, 256>>>(att_enc, att_comb);
    dec_agg<<<NN / 32, 256>>>(diff_dec, att_dec);
    gemm_dec<<<NN / 32, 256>>>(fc_dec, diff_dec, out);
}

// round 5
// speedup vs baseline: 1.0888x; 1.0888x over previous
#include <cuda_runtime.h>

#define NN 20000

// ---------------- device scratch ----------------
__device__ float g_z1 [NN * 64];
__device__ float g_hd1[NN * 64];
__device__ float g_zc [NN * 64];
__device__ float g_u  [NN * 64];

// ---------------- helpers ----------------
__device__ __forceinline__ float warpSumAll(float v) {
#pragma unroll
    for (int o = 16; o > 0; o >>= 1) v += __shfl_xor_sync(0xffffffffu, v, o);
    return v;
}
__device__ __forceinline__ float warpMaxAll(float v) {
#pragma unroll
    for (int o = 16; o > 0; o >>= 1) v = fmaxf(v, __shfl_xor_sync(0xffffffffu, v, o));
    return v;
}
__device__ __forceinline__ float lrelu(float x) { return x > 0.f ? x : 0.01f * x; }

__device__ __forceinline__ float eluf(float x) {
    if (x > 0.f) return x;
    if (x > -0.25f)
        return x * (1.f + x * (0.5f + x * (0.16666667f + x * 0.041666667f)));
    return __expf(x) - 1.f;
}

union F2U { float2 f; unsigned long long u; };
// c += a * b elementwise (packed dual-fp32 FMA)
__device__ __forceinline__ void fma2(float2& c, float2 a, float2 b) {
    F2U A, B, C; A.f = a; B.f = b; C.f = c;
    asm("fma.rn.f32x2 %0, %1, %2, %0;" : "+l"(C.u) : "l"(A.u), "l"(B.u));
    c = C.f;
}

// =====================================================================
// GEMM: block=128 (4 warps), 32 nodes/block (grid=625), warp -> 8 nodes.
// Lane l owns output dims {2l,2l+1} and {2l+64,2l+65}.
// A staged float4-DUPLICATED per 2k: As4[row][k2]=(a,a,a',a') -> one broadcast
// LDS.128 per node per 2k gives two FFMA2-ready pairs, zero splat MOVs.
// W staged k-major lane-interleaved: Ws[k][4l..4l+3] -> one LDS.128 per k.
// Per warp per 2k: 16 crossbar phases vs 32 FFMA2 -> FMA/crossbar parity.
// =====================================================================

// ---------------- encoder GEMM: Z = h@fcE^T, HD = h@dfE^T ----------------
__global__ __launch_bounds__(128, 4) void gemm_enc(const float* __restrict__ A,
                                                   const float* __restrict__ fcE,
                                                   const float* __restrict__ dfE,
                                                   float* __restrict__ Z,
                                                   float* __restrict__ HD) {
    __shared__ __align__(16) float4 As4[32][16];
    __shared__ __align__(16) float  Ws[32][132];

    const int t = threadIdx.x, lane = t & 31, w = t >> 5;
    const int node0 = blockIdx.x * 32;

    float2 acc[8][2];
#pragma unroll
    for (int i = 0; i < 8; i++) { acc[i][0] = make_float2(0.f, 0.f); acc[i][1] = make_float2(0.f, 0.f); }

    for (int ch = 0; ch < 4; ch++) {
        const int kk = ch * 32;
#pragma unroll
        for (int idx = t; idx < 32 * 32; idx += 128) {
            int row = idx >> 5, k = idx & 31;
            float v = A[(node0 + row) * 128 + kk + k];
            ((float2*)&As4[row][0])[k] = make_float2(v, v);
        }
#pragma unroll
        for (int idx = t; idx < 128 * 32; idx += 128) {
            int od = idx >> 5, k = idx & 31;
            float v = (od < 64) ? fcE[od * 128 + kk + k] : dfE[(od - 64) * 128 + kk + k];
            int l2  = (od & 63) >> 1;
            int sub = ((od >> 6) << 1) | (od & 1);
            Ws[k][4 * l2 + sub] = v;
        }
        __syncthreads();

#pragma unroll 4
        for (int k2 = 0; k2 < 16; k2++) {
            const float4 wv0 = *(const float4*)&Ws[2 * k2][4 * lane];
            const float4 wv1 = *(const float4*)&Ws[2 * k2 + 1][4 * lane];
            const float2 p00 = make_float2(wv0.x, wv0.y), p01 = make_float2(wv0.z, wv0.w);
            const float2 p10 = make_float2(wv1.x, wv1.y), p11 = make_float2(wv1.z, wv1.w);
#pragma unroll
            for (int i = 0; i < 8; i++) {
                const float4 av = As4[w * 8 + i][k2];
                const float2 a0 = make_float2(av.x, av.y);
                const float2 a1 = make_float2(av.z, av.w);
                fma2(acc[i][0], a0, p00);
                fma2(acc[i][1], a0, p01);
                fma2(acc[i][0], a1, p10);
                fma2(acc[i][1], a1, p11);
            }
        }
        __syncthreads();
    }

#pragma unroll
    for (int i = 0; i < 8; i++) {
        int node = node0 + w * 8 + i;
        ((float2*)(Z  + node * 64))[lane] = acc[i][0];
        ((float2*)(HD + node * 64))[lane] = acc[i][1];
    }
}

// ---------------- decoder GEMM: out = zc@fcD^T + u@diffD^T ----------------
__global__ __launch_bounds__(128, 4) void gemm_dec(const float* __restrict__ fcD,
                                                   const float* __restrict__ diffD,
                                                   float* __restrict__ out) {
    __shared__ __align__(16) float4 As4[32][16];
    __shared__ __align__(16) float  Ws[32][132];

    const int t = threadIdx.x, lane = t & 31, w = t >> 5;
    const int node0 = blockIdx.x * 32;

    float2 acc[8][2];
#pragma unroll
    for (int i = 0; i < 8; i++) { acc[i][0] = make_float2(0.f, 0.f); acc[i][1] = make_float2(0.f, 0.f); }

    for (int ch = 0; ch < 4; ch++) {
        const float* Asrc = (ch < 2) ? g_zc : g_u;
        const float* Wsrc = (ch < 2) ? fcD : diffD;
        const int kk = (ch & 1) * 32;
#pragma unroll
        for (int idx = t; idx < 32 * 32; idx += 128) {
            int row = idx >> 5, k = idx & 31;
            float v = Asrc[(node0 + row) * 64 + kk + k];
            ((float2*)&As4[row][0])[k] = make_float2(v, v);
        }
#pragma unroll
        for (int idx = t; idx < 128 * 32; idx += 128) {
            int od = idx >> 5, k = idx & 31;
            float v = Wsrc[od * 64 + kk + k];
            int l2  = (od & 63) >> 1;
            int sub = ((od >> 6) << 1) | (od & 1);
            Ws[k][4 * l2 + sub] = v;
        }
        __syncthreads();

#pragma unroll 4
        for (int k2 = 0; k2 < 16; k2++) {
            const float4 wv0 = *(const float4*)&Ws[2 * k2][4 * lane];
            const float4 wv1 = *(const float4*)&Ws[2 * k2 + 1][4 * lane];
            const float2 p00 = make_float2(wv0.x, wv0.y), p01 = make_float2(wv0.z, wv0.w);
            const float2 p10 = make_float2(wv1.x, wv1.y), p11 = make_float2(wv1.z, wv1.w);
#pragma unroll
            for (int i = 0; i < 8; i++) {
                const float4 av = As4[w * 8 + i][k2];
                const float2 a0 = make_float2(av.x, av.y);
                const float2 a1 = make_float2(av.z, av.w);
                fma2(acc[i][0], a0, p00);
                fma2(acc[i][1], a0, p01);
                fma2(acc[i][0], a1, p10);
                fma2(acc[i][1], a1, p11);
            }
        }
        __syncthreads();
    }

#pragma unroll
    for (int i = 0; i < 8; i++) {
        int node = node0 + w * 8 + i;
        ((float2*)(out + node * 128))[lane]      = acc[i][0];
        ((float2*)(out + node * 128 + 64))[lane] = acc[i][1];
    }
}

// ---------------- encoder aggregation: 3 hops + hop-attention combine ----------------
__global__ __launch_bounds__(256) void enc_agg(const float* __restrict__ attE,
                                               const float* __restrict__ attC) {
    __shared__ __align__(16) float hdT[56][66];
    __shared__ float sT[56];
    __shared__ __align__(16) float wS[3][25][36];
    __shared__ float sAe[64], sAc[64];

    const int t = threadIdx.x, w = t >> 5, lane = t & 31;
    const int nodeBase = blockIdx.x * 32;
    const int nl0 = w * 4;

    if (t < 64) { sAe[t] = attE[t]; sAc[t] = attC[t]; }

    for (int r = w; r < 56; r += 8) {
        int g = nodeBase - 24 + r;
        if (g < 0) g += NN;
        ((float2*)hdT[r])[lane] = ((const float2*)(g_hd1 + g * 64))[lane];
    }
    __syncthreads();

    for (int r = w; r < 56; r += 8) {
        float2 hv = ((float2*)hdT[r])[lane];
        float p = warpSumAll(hv.x * sAe[2 * lane] + hv.y * sAe[2 * lane + 1]);
        if (lane == 0) sT[r] = p;
    }
    __syncthreads();

#pragma unroll
    for (int j = 0; j < 4; j++) {
        const int li = 24 + nl0 + j;
        const float s_i = sT[li];
        float el = (lane < 25) ? lrelu(sT[li - lane] - s_i) : -1e30f;
        const float m1 = warpMaxAll(lane < 9  ? el : -1e30f);
        const float m2 = warpMaxAll(lane < 17 ? el : -1e30f);
        const float m3 = warpMaxAll(el);
        const float ex1 = (lane < 9)  ? __expf(el - m1) : 0.f;
        const float ex2 = (lane < 17) ? __expf(el - m2) : 0.f;
        const float ex3 = (lane < 25) ? __expf(el - m3) : 0.f;
        const float r1 = 1.f / warpSumAll(ex1);
        const float r2 = 1.f / warpSumAll(ex2);
        const float r3 = 1.f / warpSumAll(ex3);
        if (lane < 25) {
            wS[0][lane][nl0 + j] = ex1 * r1;
            wS[1][lane][nl0 + j] = ex2 * r2;
            wS[2][lane][nl0 + j] = ex3 * r3;
        }
    }
    __syncwarp();

    float2 A[4][3];
#pragma unroll
    for (int j = 0; j < 4; j++)
#pragma unroll
        for (int hh = 0; hh < 3; hh++) A[j][hh] = make_float2(0.f, 0.f);

#pragma unroll
    for (int tt = 0; tt < 25; tt++) {
        const float4 w3 = *(const float4*)&wS[2][tt][nl0];
        float4 w2, w1;
        if (tt < 17) w2 = *(const float4*)&wS[1][tt][nl0];
        if (tt < 9)  w1 = *(const float4*)&wS[0][tt][nl0];
#pragma unroll
        for (int j = 0; j < 4; j++) {
            const float2 hv = ((float2*)hdT[24 + nl0 + j - tt])[lane];
            const float g3 = ((const float*)&w3)[j];
            A[j][2].x = fmaf(g3, hv.x, A[j][2].x);
            A[j][2].y = fmaf(g3, hv.y, A[j][2].y);
            if (tt < 17) {
                const float g2 = ((const float*)&w2)[j];
                A[j][1].x = fmaf(g2, hv.x, A[j][1].x);
                A[j][1].y = fmaf(g2, hv.y, A[j][1].y);
            }
            if (tt < 9) {
                const float g1 = ((const float*)&w1)[j];
                A[j][0].x = fmaf(g1, hv.x, A[j][0].x);
                A[j][0].y = fmaf(g1, hv.y, A[j][0].y);
            }
        }
    }

    const float ac0 = sAc[2 * lane], ac1 = sAc[2 * lane + 1];
#pragma unroll
    for (int j = 0; j < 4; j++) {
        const int li = 24 + nl0 + j;
        const int node = nodeBase + nl0 + j;
        const float2 hvi = ((float2*)hdT[li])[lane];
        const float2 zv  = ((const float2*)(g_z1 + node * 64))[lane];
        float2 Z1, Z2, Z3;
        Z1.x = eluf(zv.x + A[j][0].x - hvi.x); Z1.y = eluf(zv.y + A[j][0].y - hvi.y);
        Z2.x = eluf(zv.x + A[j][1].x - hvi.x); Z2.y = eluf(zv.y + A[j][1].y - hvi.y);
        Z3.x = eluf(zv.x + A[j][2].x - hvi.x); Z3.y = eluf(zv.y + A[j][2].y - hvi.y);

        const float c1 = warpSumAll(Z1.x * ac0 + Z1.y * ac1);
        const float c2 = warpSumAll(Z2.x * ac0 + Z2.y * ac1);
        const float c3 = warpSumAll(Z3.x * ac0 + Z3.y * ac1);
        const float l1 = lrelu(c1), l2 = lrelu(c2), l3 = lrelu(c3);
        const float mx = fmaxf(l1, fmaxf(l2, l3));
        const float e1 = __expf(l1 - mx), e2 = __expf(l2 - mx), e3 = __expf(l3 - mx);
        const float rd = 1.f / (e1 + e2 + e3);

        float2 o;
        o.x = (e1 * Z1.x + e2 * Z2.x + e3 * Z3.x) * rd;
        o.y = (e1 * Z1.y + e2 * Z2.y + e3 * Z3.y) * rd;
        ((float2*)(g_zc + node * 64))[lane] = o;
    }
}

// ---------------- decoder aggregation in 64-dim latent ----------------
__global__ __launch_bounds__(256) void dec_agg(const float* __restrict__ diffD,
                                               const float* __restrict__ attD) {
    __shared__ __align__(16) float zT[56][66];
    __shared__ float sT[56];
    __shared__ __align__(16) float wS[25][36];
    __shared__ float sv[64];

    const int t = threadIdx.x, w = t >> 5, lane = t & 31;
    const int nodeBase = blockIdx.x * 32;
    const int nl0 = w * 4;

    if (t < 64) {
        float a = 0.f;
#pragma unroll 4
        for (int od = 0; od < 128; od++) a = fmaf(diffD[od * 64 + t], attD[od], a);
        sv[t] = a;
    }

    for (int r = w; r < 56; r += 8) {
        int g = nodeBase - 24 + r;
        if (g < 0) g += NN;
        ((float2*)zT[r])[lane] = ((const float2*)(g_zc + g * 64))[lane];
    }
    __syncthreads();

    for (int r = w; r < 56; r += 8) {
        float2 zv = ((float2*)zT[r])[lane];
        float p = warpSumAll(zv.x * sv[2 * lane] + zv.y * sv[2 * lane + 1]);
        if (lane == 0) sT[r] = p;
    }
    __syncthreads();

#pragma unroll
    for (int j = 0; j < 4; j++) {
        const int li = 24 + nl0 + j;
        const float s_i = sT[li];
        float el = (lane < 25) ? lrelu(sT[li - lane] - s_i) : -1e30f;
        const float m = warpMaxAll(el);
        const float ex = (lane < 25) ? __expf(el - m) : 0.f;
        const float rd = 1.f / warpSumAll(ex);
        if (lane < 25) wS[lane][nl0 + j] = ex * rd;
    }
    __syncwarp();

    float2 A[4];
#pragma unroll
    for (int j = 0; j < 4; j++) A[j] = make_float2(0.f, 0.f);

#pragma unroll
    for (int tt = 0; tt < 25; tt++) {
        const float4 wv = *(const float4*)&wS[tt][nl0];
#pragma unroll
        for (int j = 0; j < 4; j++) {
            const float2 zv = ((float2*)zT[24 + nl0 + j - tt])[lane];
            const float g = ((const float*)&wv)[j];
            A[j].x = fmaf(g, zv.x, A[j].x);
            A[j].y = fmaf(g, zv.y, A[j].y);
        }
    }

#pragma unroll
    for (int j = 0; j < 4; j++) {
        const int node = nodeBase + nl0 + j;
        const float2 zvi = ((float2*)zT[24 + nl0 + j])[lane];
        float2 o;
        o.x = A[j].x - zvi.x;
        o.y = A[j].y - zvi.y;
        ((float2*)(g_u + node * 64))[lane] = o;
    }
}

// ---------------- launch ----------------
extern "C" void kernel_launch(void* const* d_in, const int* in_sizes, int n_in,
                              void* d_out, int out_size) {
    const float* h        = (const float*)d_in[0];
    const float* fc_enc   = (const float*)d_in[1];
    const float* diff_enc = (const float*)d_in[2];
    const float* att_enc  = (const float*)d_in[3];
    const float* fc_dec   = (const float*)d_in[4];
    const float* diff_dec = (const float*)d_in[5];
    const float* att_dec  = (const float*)d_in[6];
    const float* att_comb = (const float*)d_in[7];
    float* out = (float*)d_out;

    void *p;
    cudaGetSymbolAddress(&p, g_z1);  float* z1  = (float*)p;
    cudaGetSymbolAddress(&p, g_hd1); float* hd1 = (float*)p;

    gemm_enc<<<NN / 32, 128>>>(h, fc_enc, diff_enc, z1, hd1);
    enc_agg<<<NN / 32, 256>>>(att_enc, att_comb);
    dec_agg<<<NN / 32, 256>>>(diff_dec, att_dec);
    gemm_dec<<<NN / 32, 128>>>(fc_dec, diff_dec, out);
}